// round 1
// baseline (speedup 1.0000x reference)
#include <cuda_runtime.h>

#define NN 256      // batch
#define PP 128      // points per polygon
#define TIMEI 10
#define NT (PP * TIMEI)   // 1280 interpolated targets

// per-block partials: s1, c1, s2, c2 for each of NN rows
__device__ float g_part[NN * 4];

__device__ __forceinline__ float smooth_l1(float p, float t) {
    float diff = fabsf(p - t);
    // BETA = 0.25: diff < beta ? 0.5*d*d/beta : d - 0.5*beta
    return diff < 0.25f ? 2.0f * diff * diff : diff - 0.125f;
}

__global__ __launch_bounds__(PP) void dm_main(
    const float* __restrict__ pred_c,
    const float* __restrict__ pred_o,
    const float* __restrict__ gt_c,
    const float* __restrict__ gt_k,
    const int*   __restrict__ gt_m)
{
    __shared__ float4 s_tab[NT];    // (e=-2tx, f=-2ty, g=tx^2+ty^2, pad)
    __shared__ float2 s_gt[PP];
    __shared__ float2 s_pred[PP];
    __shared__ float2 s_po[PP];
    __shared__ float  s_red[4][4];  // [quantity][warp]

    const int n = blockIdx.x;
    const int t = threadIdx.x;

    const float2* pc2 = reinterpret_cast<const float2*>(pred_c) + (size_t)n * PP;
    const float2* po2 = reinterpret_cast<const float2*>(pred_o) + (size_t)n * PP;
    const float2* gc2 = reinterpret_cast<const float2*>(gt_c)   + (size_t)n * PP;
    const float2* gk2 = reinterpret_cast<const float2*>(gt_k)   + (size_t)n * PP;

    float2 myp = pc2[t];
    float2 myo = po2[t];
    s_pred[t] = myp;
    s_po[t]   = myo;
    s_gt[t]   = gc2[t];
    __syncthreads();

    // ---- build interpolation table: target[p*10+k] = gt[p]*s + gt[p-1]*(1-s)
    {
        float2 a = s_gt[t];
        float2 b = s_gt[(t + PP - 1) & (PP - 1)];
        #pragma unroll
        for (int k = 0; k < TIMEI; ++k) {
            float s  = (float)k / (float)TIMEI;
            float om = 1.0f - s;
            float tx = a.x * s + b.x * om;
            float ty = a.y * s + b.y * om;
            s_tab[t * TIMEI + k] =
                make_float4(-2.0f * tx, -2.0f * ty, tx * tx + ty * ty, 0.0f);
        }
    }
    __syncthreads();

    // ---- item 1: per pred point, argmin over 1280 targets of
    //      score = px*e + py*f + g  (equals dist^2 minus per-thread constant)
    const float px = myp.x, py = myp.y;
    float best[8];
    int   bj[8];
    #pragma unroll
    for (int u = 0; u < 8; ++u) { best[u] = 3.4e38f; bj[u] = 0; }

    for (int j = 0; j < NT; j += 8) {
        #pragma unroll
        for (int u = 0; u < 8; ++u) {
            float4 e = s_tab[j + u];
            float sc = fmaf(px, e.x, fmaf(py, e.y, e.z));
            if (sc < best[u]) { best[u] = sc; bj[u] = j + u; }
        }
    }
    float bsc = best[0]; int bidx = bj[0];
    #pragma unroll
    for (int u = 1; u < 8; ++u) {
        if (best[u] < bsc || (best[u] == bsc && bj[u] < bidx)) {
            bsc = best[u]; bidx = bj[u];
        }
    }

    float s1 = 0.0f, c1 = 0.0f;
    {
        float4 e = s_tab[bidx];
        float tx = -0.5f * e.x, ty = -0.5f * e.y;   // exact recovery
        float dx = px - tx, dy = py - ty;
        float d2 = dx * dx + dy * dy;               // matched1
        if (d2 <= 1.0e6f) {
            float ox = (tx - px) * 0.25f;
            float oy = (ty - py) * 0.25f;
            s1 = smooth_l1(myo.x, ox) + smooth_l1(myo.y, oy);
            c1 = 1.0f;
        }
    }

    // ---- item 2: per gt key point, argmin over 128 pred points
    float2 kk = gk2[t];
    int    mk = gt_m[n * PP + t];
    float b2[4]; int j2[4];
    #pragma unroll
    for (int u = 0; u < 4; ++u) { b2[u] = 3.4e38f; j2[u] = 0; }
    for (int j = 0; j < PP; j += 4) {
        #pragma unroll
        for (int u = 0; u < 4; ++u) {
            float2 pr = s_pred[j + u];
            float dx = kk.x - pr.x, dy = kk.y - pr.y;
            float d  = fmaf(dx, dx, dy * dy);
            if (d < b2[u]) { b2[u] = d; j2[u] = j + u; }
        }
    }
    float b2m = b2[0]; int j2m = j2[0];
    #pragma unroll
    for (int u = 1; u < 4; ++u) {
        if (b2[u] < b2m || (b2[u] == b2m && j2[u] < j2m)) {
            b2m = b2[u]; j2m = j2[u];
        }
    }

    float s2 = 0.0f, c2 = 0.0f;
    if (mk && b2m <= 1.0e6f) {
        float2 pg = s_pred[j2m];
        float2 og = s_po[j2m];
        float ox = (kk.x - pg.x) * 0.25f;
        float oy = (kk.y - pg.y) * 0.25f;
        s2 = smooth_l1(og.x, ox) + smooth_l1(og.y, oy);
        c2 = 1.0f;
    }

    // ---- deterministic block reduction (fixed shuffle tree + fixed order)
    #pragma unroll
    for (int o = 16; o > 0; o >>= 1) {
        s1 += __shfl_down_sync(0xffffffffu, s1, o);
        c1 += __shfl_down_sync(0xffffffffu, c1, o);
        s2 += __shfl_down_sync(0xffffffffu, s2, o);
        c2 += __shfl_down_sync(0xffffffffu, c2, o);
    }
    const int w = t >> 5, l = t & 31;
    if (l == 0) {
        s_red[0][w] = s1; s_red[1][w] = c1;
        s_red[2][w] = s2; s_red[3][w] = c2;
    }
    __syncthreads();
    if (t == 0) {
        float a0 = (s_red[0][0] + s_red[0][1]) + (s_red[0][2] + s_red[0][3]);
        float a1 = (s_red[1][0] + s_red[1][1]) + (s_red[1][2] + s_red[1][3]);
        float a2 = (s_red[2][0] + s_red[2][1]) + (s_red[2][2] + s_red[2][3]);
        float a3 = (s_red[3][0] + s_red[3][1]) + (s_red[3][2] + s_red[3][3]);
        g_part[n * 4 + 0] = a0;
        g_part[n * 4 + 1] = a1;
        g_part[n * 4 + 2] = a2;
        g_part[n * 4 + 3] = a3;
    }
}

__global__ __launch_bounds__(256) void dm_final(float* __restrict__ out)
{
    __shared__ float s_red[4][8];
    const int t = threadIdx.x;           // 256 threads, one per row
    float4 v = reinterpret_cast<const float4*>(g_part)[t];
    float s1 = v.x, c1 = v.y, s2 = v.z, c2 = v.w;

    #pragma unroll
    for (int o = 16; o > 0; o >>= 1) {
        s1 += __shfl_down_sync(0xffffffffu, s1, o);
        c1 += __shfl_down_sync(0xffffffffu, c1, o);
        s2 += __shfl_down_sync(0xffffffffu, s2, o);
        c2 += __shfl_down_sync(0xffffffffu, c2, o);
    }
    const int w = t >> 5, l = t & 31;
    if (l == 0) {
        s_red[0][w] = s1; s_red[1][w] = c1;
        s_red[2][w] = s2; s_red[3][w] = c2;
    }
    __syncthreads();
    if (t == 0) {
        float t1 = 0.0f, t2 = 0.0f, t3 = 0.0f, t4 = 0.0f;
        #pragma unroll
        for (int i = 0; i < 8; ++i) {
            t1 += s_red[0][i]; t2 += s_red[1][i];
            t3 += s_red[2][i]; t4 += s_red[3][i];
        }
        float loss1 = (t1 / fmaxf(t2 * 2.0f, 1.0f)) * 0.5f;  // * (1 - KEY_W)
        float loss2 = (t3 / fmaxf(t4 * 2.0f, 1.0f)) * 0.5f;  // * KEY_W
        out[0] = loss1 + loss2;                               // * LOSS_WEIGHT
    }
}

extern "C" void kernel_launch(void* const* d_in, const int* in_sizes, int n_in,
                              void* d_out, int out_size)
{
    const float* pred_c = (const float*)d_in[0];
    const float* pred_o = (const float*)d_in[1];
    const float* gt_c   = (const float*)d_in[2];
    const float* gt_k   = (const float*)d_in[3];
    const int*   gt_m   = (const int*)d_in[4];

    dm_main<<<NN, PP>>>(pred_c, pred_o, gt_c, gt_k, gt_m);
    dm_final<<<1, 256>>>((float*)d_out);
}

// round 2
// speedup vs baseline: 1.5483x; 1.5483x over previous
#include <cuda_runtime.h>

#define NN 256      // batch
#define PP 128      // points per polygon
#define TIMEI 10
#define NT (PP * TIMEI)   // 1280 interpolated targets
#define TPB 512
#define CH  (NT / 4)      // 320 targets per h-chunk
#define PCH (PP / 4)      // 32 preds per h-chunk

__device__ float4 g_part[NN];
__device__ unsigned int g_cnt = 0;

__device__ __forceinline__ float smooth_l1(float p, float t) {
    float d = fabsf(p - t);
    // BETA = 0.25
    return d < 0.25f ? 2.0f * d * d : d - 0.125f;
}

__global__ __launch_bounds__(TPB) void dm_fused(
    const float* __restrict__ pred_c,
    const float* __restrict__ pred_o,
    const float* __restrict__ gt_c,
    const float* __restrict__ gt_k,
    const int*   __restrict__ gt_m,
    float*       __restrict__ out)
{
    __shared__ float4 s_tab[NT];     // (-2tx, -2ty, tx^2+ty^2, 0)
    __shared__ float2 s_pred[PP], s_po[PP], s_gt[PP], s_gk[PP];
    __shared__ float  s_bs[4 * PP];
    __shared__ int    s_bj[4 * PP];
    __shared__ float  s_b2[4 * PP];
    __shared__ int    s_j2[4 * PP];
    __shared__ float  s_red[4][16];
    __shared__ int    s_last;

    const int n = blockIdx.x;
    const int t = threadIdx.x;
    const int p = t & (PP - 1);
    const int h = t >> 7;

    if (t < PP) {
        const float2* pc2 = reinterpret_cast<const float2*>(pred_c) + (size_t)n * PP;
        const float2* po2 = reinterpret_cast<const float2*>(pred_o) + (size_t)n * PP;
        const float2* gc2 = reinterpret_cast<const float2*>(gt_c)   + (size_t)n * PP;
        const float2* gk2 = reinterpret_cast<const float2*>(gt_k)   + (size_t)n * PP;
        s_pred[t] = pc2[t];
        s_po[t]   = po2[t];
        s_gt[t]   = gc2[t];
        s_gk[t]   = gk2[t];
    }
    __syncthreads();

    // build interpolation table (t < 128, 10 entries each)
    if (t < PP) {
        float2 a = s_gt[t];
        float2 b = s_gt[(t + PP - 1) & (PP - 1)];
        #pragma unroll
        for (int k = 0; k < TIMEI; ++k) {
            float s  = (float)k / (float)TIMEI;
            float om = 1.0f - s;
            float tx = a.x * s + b.x * om;
            float ty = a.y * s + b.y * om;
            s_tab[t * TIMEI + k] =
                make_float4(-2.0f * tx, -2.0f * ty, tx * tx + ty * ty, 0.0f);
        }
    }
    __syncthreads();

    // ---- item 1 partial argmin: chunk h of targets for point p ----
    const float px = s_pred[p].x, py = s_pred[p].y;
    {
        float best[8]; int bj[8];
        #pragma unroll
        for (int u = 0; u < 8; ++u) { best[u] = 3.4e38f; bj[u] = 0; }
        const int base = h * CH;
        for (int j = 0; j < CH; j += 8) {
            #pragma unroll
            for (int u = 0; u < 8; ++u) {
                float4 e = s_tab[base + j + u];
                float sc = fmaf(px, e.x, fmaf(py, e.y, e.z));
                if (sc < best[u]) { best[u] = sc; bj[u] = base + j + u; }
            }
        }
        float bs = best[0]; int bi = bj[0];
        #pragma unroll
        for (int u = 1; u < 8; ++u)
            if (best[u] < bs || (best[u] == bs && bj[u] < bi)) { bs = best[u]; bi = bj[u]; }
        s_bs[t] = bs; s_bj[t] = bi;
    }

    // ---- item 2 partial argmin: chunk h of preds for key point p ----
    {
        const float kx = s_gk[p].x, ky = s_gk[p].y;
        float b2[4]; int j2[4];
        #pragma unroll
        for (int u = 0; u < 4; ++u) { b2[u] = 3.4e38f; j2[u] = 0; }
        const int pb = h * PCH;
        for (int j = 0; j < PCH; j += 4) {
            #pragma unroll
            for (int u = 0; u < 4; ++u) {
                float2 pr = s_pred[pb + j + u];
                float dx = kx - pr.x, dy = ky - pr.y;
                float d  = fmaf(dx, dx, dy * dy);
                if (d < b2[u]) { b2[u] = d; j2[u] = pb + j + u; }
            }
        }
        float bs = b2[0]; int bi = j2[0];
        #pragma unroll
        for (int u = 1; u < 4; ++u)
            if (b2[u] < bs || (b2[u] == bs && j2[u] < bi)) { bs = b2[u]; bi = j2[u]; }
        s_b2[t] = bs; s_j2[t] = bi;
    }
    __syncthreads();

    // ---- combine across h-chunks + per-point losses (t < 128) ----
    float s1 = 0.0f, c1 = 0.0f, s2 = 0.0f, c2 = 0.0f;
    if (t < PP) {
        // item 1
        float bs = s_bs[t]; int bi = s_bj[t];
        #pragma unroll
        for (int hh = 1; hh < 4; ++hh) {
            float s = s_bs[hh * PP + t]; int j = s_bj[hh * PP + t];
            if (s < bs || (s == bs && j < bi)) { bs = s; bi = j; }
        }
        {
            float4 e = s_tab[bi];
            float tx = -0.5f * e.x, ty = -0.5f * e.y;   // exact recovery
            float mpx = s_pred[t].x, mpy = s_pred[t].y;
            float dx = mpx - tx, dy = mpy - ty;
            float d2 = dx * dx + dy * dy;
            if (d2 <= 1.0e6f) {
                float2 mo = s_po[t];
                float ox = (tx - mpx) * 0.25f;
                float oy = (ty - mpy) * 0.25f;
                s1 = smooth_l1(mo.x, ox) + smooth_l1(mo.y, oy);
                c1 = 1.0f;
            }
        }
        // item 2
        float b2m = s_b2[t]; int j2m = s_j2[t];
        #pragma unroll
        for (int hh = 1; hh < 4; ++hh) {
            float s = s_b2[hh * PP + t]; int j = s_j2[hh * PP + t];
            if (s < b2m || (s == b2m && j < j2m)) { b2m = s; j2m = j; }
        }
        int mk = gt_m[n * PP + t];
        if (mk && b2m <= 1.0e6f) {
            float2 kk = s_gk[t];
            float2 pg = s_pred[j2m];
            float2 og = s_po[j2m];
            float ox = (kk.x - pg.x) * 0.25f;
            float oy = (kk.y - pg.y) * 0.25f;
            s2 = smooth_l1(og.x, ox) + smooth_l1(og.y, oy);
            c2 = 1.0f;
        }
    }

    // ---- deterministic block reduction over all 16 warps ----
    #pragma unroll
    for (int o = 16; o > 0; o >>= 1) {
        s1 += __shfl_down_sync(0xffffffffu, s1, o);
        c1 += __shfl_down_sync(0xffffffffu, c1, o);
        s2 += __shfl_down_sync(0xffffffffu, s2, o);
        c2 += __shfl_down_sync(0xffffffffu, c2, o);
    }
    const int w = t >> 5, l = t & 31;
    if (l == 0) {
        s_red[0][w] = s1; s_red[1][w] = c1;
        s_red[2][w] = s2; s_red[3][w] = c2;
    }
    __syncthreads();
    if (t == 0) {
        float a0 = 0.f, a1 = 0.f, a2 = 0.f, a3 = 0.f;
        #pragma unroll
        for (int i = 0; i < 16; ++i) {
            a0 += s_red[0][i]; a1 += s_red[1][i];
            a2 += s_red[2][i]; a3 += s_red[3][i];
        }
        g_part[n] = make_float4(a0, a1, a2, a3);
        __threadfence();
        unsigned int v = atomicAdd(&g_cnt, 1u);
        s_last = (v == (unsigned)(NN - 1));
    }
    __syncthreads();

    // ---- last block: fixed-order final reduction (bitwise deterministic) ----
    if (s_last) {
        float f1 = 0.f, f2 = 0.f, f3 = 0.f, f4 = 0.f;
        if (t < NN) {
            float4 v = g_part[t];
            f1 = v.x; f2 = v.y; f3 = v.z; f4 = v.w;
        }
        #pragma unroll
        for (int o = 16; o > 0; o >>= 1) {
            f1 += __shfl_down_sync(0xffffffffu, f1, o);
            f2 += __shfl_down_sync(0xffffffffu, f2, o);
            f3 += __shfl_down_sync(0xffffffffu, f3, o);
            f4 += __shfl_down_sync(0xffffffffu, f4, o);
        }
        __syncthreads();   // re-use s_red safely
        if (l == 0) {
            s_red[0][w] = f1; s_red[1][w] = f2;
            s_red[2][w] = f3; s_red[3][w] = f4;
        }
        __syncthreads();
        if (t == 0) {
            float t1 = 0.f, t2 = 0.f, t3 = 0.f, t4 = 0.f;
            #pragma unroll
            for (int i = 0; i < 16; ++i) {
                t1 += s_red[0][i]; t2 += s_red[1][i];
                t3 += s_red[2][i]; t4 += s_red[3][i];
            }
            float loss1 = (t1 / fmaxf(t2 * 2.0f, 1.0f)) * 0.5f;  // * (1 - KEY_W)
            float loss2 = (t3 / fmaxf(t4 * 2.0f, 1.0f)) * 0.5f;  // * KEY_W
            out[0] = loss1 + loss2;
            g_cnt = 0;   // reset for next graph replay
        }
    }
}

extern "C" void kernel_launch(void* const* d_in, const int* in_sizes, int n_in,
                              void* d_out, int out_size)
{
    const float* pred_c = (const float*)d_in[0];
    const float* pred_o = (const float*)d_in[1];
    const float* gt_c   = (const float*)d_in[2];
    const float* gt_k   = (const float*)d_in[3];
    const int*   gt_m   = (const int*)d_in[4];

    dm_fused<<<NN, TPB>>>(pred_c, pred_o, gt_c, gt_k, gt_m, (float*)d_out);
}

// round 3
// speedup vs baseline: 2.5553x; 1.6504x over previous
#include <cuda_runtime.h>

#define NN 256      // batch
#define PP 128      // points per polygon (= segments)
#define TIMEI 10
#define TPB 512
#define SCH (PP / 4)      // 32 segments per h-chunk
#define PCH (PP / 4)      // 32 preds per h-chunk

__device__ float4 g_part[NN];
__device__ unsigned int g_cnt = 0;

__device__ __forceinline__ float smooth_l1(float p, float t) {
    float d = fabsf(p - t);
    return d < 0.25f ? 2.0f * d * d : d - 0.125f;   // BETA = 0.25
}

__global__ __launch_bounds__(TPB) void dm_fused(
    const float* __restrict__ pred_c,
    const float* __restrict__ pred_o,
    const float* __restrict__ gt_c,
    const float* __restrict__ gt_k,
    const int*   __restrict__ gt_m,
    float*       __restrict__ out)
{
    // segment tables: A = (e0, f0, g0, g1), B = (de, df, g2, -0.5/g2)
    // score(p,k) = px*e(k)+py*f(k)+g(k),  e(k)=e0+k*de, f(k)=f0+k*df,
    // g(k)=g0+k*g1+k^2*g2  ->  alpha + beta*k + gamma*k^2
    __shared__ float4 s_tA[PP], s_tB[PP];
    __shared__ float4 s_pt[PP];                 // pred score table (-2px,-2py,|p|^2,0)
    __shared__ float2 s_pred[PP], s_po[PP], s_gt[PP], s_gk[PP];
    __shared__ float  s_bs[4 * PP];
    __shared__ float  s_bi[4 * PP];             // packed float index 16*p + k
    __shared__ float  s_b2[4 * PP];
    __shared__ int    s_j2[4 * PP];
    __shared__ float  s_red[4][16];
    __shared__ int    s_last;

    const int n = blockIdx.x;
    const int t = threadIdx.x;
    const int p = t & (PP - 1);
    const int h = t >> 7;

    if (t < PP) {
        const float2* pc2 = reinterpret_cast<const float2*>(pred_c) + (size_t)n * PP;
        const float2* po2 = reinterpret_cast<const float2*>(pred_o) + (size_t)n * PP;
        const float2* gc2 = reinterpret_cast<const float2*>(gt_c)   + (size_t)n * PP;
        const float2* gk2 = reinterpret_cast<const float2*>(gt_k)   + (size_t)n * PP;
        s_pred[t] = pc2[t];
        s_po[t]   = po2[t];
        s_gt[t]   = gc2[t];
        s_gk[t]   = gk2[t];
    }
    __syncthreads();

    if (t < PP) {
        float2 a = s_gt[t];
        float2 b = s_gt[(t + PP - 1) & (PP - 1)];     // k=0 target is b
        float dx = (a.x - b.x) * 0.1f;
        float dy = (a.y - b.y) * 0.1f;
        float g2 = dx * dx + dy * dy;
        float inv = (g2 > 0.0f) ? (-0.5f / g2) : 0.0f;
        s_tA[t] = make_float4(-2.0f * b.x, -2.0f * b.y,
                              b.x * b.x + b.y * b.y,
                              2.0f * (b.x * dx + b.y * dy));
        s_tB[t] = make_float4(-2.0f * dx, -2.0f * dy, g2, inv);
        float2 pr = s_pred[t];
        s_pt[t] = make_float4(-2.0f * pr.x, -2.0f * pr.y,
                              pr.x * pr.x + pr.y * pr.y, 0.0f);
    }
    __syncthreads();

    // ---- item 1: chunk h of segments, closed-form best k per segment ----
    const float px = s_pred[p].x, py = s_pred[p].y;
    {
        float val[4]; float bif[4];
        #pragma unroll
        for (int u = 0; u < 4; ++u) { val[u] = 3.4e38f; bif[u] = 0.0f; }
        const int base = h * SCH;
        for (int j = 0; j < SCH; j += 4) {
            #pragma unroll
            for (int u = 0; u < 4; ++u) {
                const int sg = base + j + u;
                float4 A = s_tA[sg];
                float4 B = s_tB[sg];
                float alpha = fmaf(px, A.x, fmaf(py, A.y, A.z));
                float beta  = fmaf(px, B.x, fmaf(py, B.y, A.w));
                float kf = beta * B.w;                      // vertex
                kf = fminf(fmaxf(kf, 0.0f), 9.0f);
                kf = rintf(kf);
                float v = fmaf(kf, fmaf(kf, B.z, beta), alpha);
                float bi = kf + (float)(16 * sg);           // packed 16*p + k
                if (v < val[u]) { val[u] = v; bif[u] = bi; }
            }
        }
        float bs = val[0]; float bi = bif[0];
        #pragma unroll
        for (int u = 1; u < 4; ++u)
            if (val[u] < bs || (val[u] == bs && bif[u] < bi)) { bs = val[u]; bi = bif[u]; }
        s_bs[t] = bs; s_bi[t] = bi;
    }

    // ---- item 2: chunk h of preds for key point p (score form) ----
    {
        const float kx = s_gk[p].x, ky = s_gk[p].y;
        float b2[4]; int j2[4];
        #pragma unroll
        for (int u = 0; u < 4; ++u) { b2[u] = 3.4e38f; j2[u] = 0; }
        const int pb = h * PCH;
        for (int j = 0; j < PCH; j += 4) {
            #pragma unroll
            for (int u = 0; u < 4; ++u) {
                float4 E = s_pt[pb + j + u];
                float d = fmaf(kx, E.x, fmaf(ky, E.y, E.z));
                if (d < b2[u]) { b2[u] = d; j2[u] = pb + j + u; }
            }
        }
        float bs = b2[0]; int bi = j2[0];
        #pragma unroll
        for (int u = 1; u < 4; ++u)
            if (b2[u] < bs || (b2[u] == bs && j2[u] < bi)) { bs = b2[u]; bi = j2[u]; }
        s_b2[t] = bs; s_j2[t] = bi;
    }
    __syncthreads();

    // ---- combine across h-chunks + per-point losses (t < 128) ----
    float s1 = 0.0f, c1 = 0.0f, s2 = 0.0f, c2 = 0.0f;
    if (t < PP) {
        // item 1
        float bs = s_bs[t]; float bif = s_bi[t];
        #pragma unroll
        for (int hh = 1; hh < 4; ++hh) {
            float s = s_bs[hh * PP + t]; float b = s_bi[hh * PP + t];
            if (s < bs || (s == bs && b < bif)) { bs = s; bif = b; }
        }
        {
            int bi = (int)bif;
            int sg = bi >> 4;
            float kf = (float)(bi & 15);
            float4 A = s_tA[sg];
            float4 B = s_tB[sg];
            float tx = -0.5f * fmaf(kf, B.x, A.x);          // e(k) -> tx
            float ty = -0.5f * fmaf(kf, B.y, A.y);
            float mpx = s_pred[t].x, mpy = s_pred[t].y;
            float dxx = mpx - tx, dyy = mpy - ty;
            float d2 = dxx * dxx + dyy * dyy;
            if (d2 <= 1.0e6f) {
                float2 mo = s_po[t];
                float ox = (tx - mpx) * 0.25f;
                float oy = (ty - mpy) * 0.25f;
                s1 = smooth_l1(mo.x, ox) + smooth_l1(mo.y, oy);
                c1 = 1.0f;
            }
        }
        // item 2
        float b2m = s_b2[t]; int j2m = s_j2[t];
        #pragma unroll
        for (int hh = 1; hh < 4; ++hh) {
            float s = s_b2[hh * PP + t]; int j = s_j2[hh * PP + t];
            if (s < b2m || (s == b2m && j < j2m)) { b2m = s; j2m = j; }
        }
        int mk = gt_m[n * PP + t];
        float2 kk = s_gk[t];
        float kk2 = kk.x * kk.x + kk.y * kk.y;              // restore dist^2
        if (mk && (b2m + kk2) <= 1.0e6f) {
            float2 pg = s_pred[j2m];
            float2 og = s_po[j2m];
            float ox = (kk.x - pg.x) * 0.25f;
            float oy = (kk.y - pg.y) * 0.25f;
            s2 = smooth_l1(og.x, ox) + smooth_l1(og.y, oy);
            c2 = 1.0f;
        }
    }

    // ---- deterministic block reduction over all 16 warps ----
    #pragma unroll
    for (int o = 16; o > 0; o >>= 1) {
        s1 += __shfl_down_sync(0xffffffffu, s1, o);
        c1 += __shfl_down_sync(0xffffffffu, c1, o);
        s2 += __shfl_down_sync(0xffffffffu, s2, o);
        c2 += __shfl_down_sync(0xffffffffu, c2, o);
    }
    const int w = t >> 5, l = t & 31;
    if (l == 0) {
        s_red[0][w] = s1; s_red[1][w] = c1;
        s_red[2][w] = s2; s_red[3][w] = c2;
    }
    __syncthreads();
    if (t == 0) {
        float a0 = 0.f, a1 = 0.f, a2 = 0.f, a3 = 0.f;
        #pragma unroll
        for (int i = 0; i < 16; ++i) {
            a0 += s_red[0][i]; a1 += s_red[1][i];
            a2 += s_red[2][i]; a3 += s_red[3][i];
        }
        g_part[n] = make_float4(a0, a1, a2, a3);
        __threadfence();
        unsigned int v = atomicAdd(&g_cnt, 1u);
        s_last = (v == (unsigned)(NN - 1));
    }
    __syncthreads();

    // ---- last block: fixed-order final reduction (bitwise deterministic) ----
    if (s_last) {
        float f1 = 0.f, f2 = 0.f, f3 = 0.f, f4 = 0.f;
        if (t < NN) {
            float4 v = g_part[t];
            f1 = v.x; f2 = v.y; f3 = v.z; f4 = v.w;
        }
        #pragma unroll
        for (int o = 16; o > 0; o >>= 1) {
            f1 += __shfl_down_sync(0xffffffffu, f1, o);
            f2 += __shfl_down_sync(0xffffffffu, f2, o);
            f3 += __shfl_down_sync(0xffffffffu, f3, o);
            f4 += __shfl_down_sync(0xffffffffu, f4, o);
        }
        __syncthreads();
        if (l == 0) {
            s_red[0][w] = f1; s_red[1][w] = f2;
            s_red[2][w] = f3; s_red[3][w] = f4;
        }
        __syncthreads();
        if (t == 0) {
            float t1 = 0.f, t2 = 0.f, t3 = 0.f, t4 = 0.f;
            #pragma unroll
            for (int i = 0; i < 16; ++i) {
                t1 += s_red[0][i]; t2 += s_red[1][i];
                t3 += s_red[2][i]; t4 += s_red[3][i];
            }
            float loss1 = (t1 / fmaxf(t2 * 2.0f, 1.0f)) * 0.5f;  // * (1 - KEY_W)
            float loss2 = (t3 / fmaxf(t4 * 2.0f, 1.0f)) * 0.5f;  // * KEY_W
            out[0] = loss1 + loss2;
            g_cnt = 0;   // reset for next graph replay
        }
    }
}

extern "C" void kernel_launch(void* const* d_in, const int* in_sizes, int n_in,
                              void* d_out, int out_size)
{
    const float* pred_c = (const float*)d_in[0];
    const float* pred_o = (const float*)d_in[1];
    const float* gt_c   = (const float*)d_in[2];
    const float* gt_k   = (const float*)d_in[3];
    const int*   gt_m   = (const int*)d_in[4];

    dm_fused<<<NN, TPB>>>(pred_c, pred_o, gt_c, gt_k, gt_m, (float*)d_out);
}